// round 9
// baseline (speedup 1.0000x reference)
#include <cuda_runtime.h>
#include <cuda_bf16.h>
#include <stdint.h>

#define TN 2000
#define UN 50000
#define TF 16
#define OUTC (TF + 36)
#define NF 40                   // padded features: 0..35 emb, 36 count, 37..39 zero
#define KPAD 50176              // mult of 64
#define KT2 64                  // K per pipeline stage
#define NST_TOT (KPAD / KT2)    // 784
#define MB 128                  // M per CTA (4 warps x m32)
#define NMB 16
#define TPAD (NMB * MB)         // 2048
#define NSPLIT 18               // grid = 288 CTAs, all resident at 2/SM
#define NTHR 128
#define ASTR 72                              // A row stride (ints): conflict-free
#define ASTAGE_B (128 * ASTR * 4)            // 36864 B
#define BSTR 40                              // B row stride (words): conflict-free
#define BSTAGE_B (NF * BSTR * 4)             // 6400 B
#define SMEM_TOTAL (2 * (ASTAGE_B + BSTAGE_B))   // 86528 B

// table geometry (FEATURE_LIST = 222,27,373,283,26,7)
#define TROWS 938
#define TFLOATS (TROWS * 6)     // 5628 floats = 22512 B

// ---------------- device scratch (static, zero-init; rows 37-39 & k-tail stay 0) ---
__device__ __nv_bfloat16 g_UT[(size_t)NF * KPAD];   // paired-word layout per 64k block
__device__ float g_part[(size_t)NSPLIT * TPAD * NF];

__device__ __forceinline__ uint32_t smem_u32(const void* p) {
    uint32_t a;
    asm("{ .reg .u64 t; cvta.to.shared.u64 t, %1; cvt.u32.u64 %0, t; }" : "=r"(a) : "l"(p));
    return a;
}
__device__ __forceinline__ void mma16816(float* c, uint32_t a0, uint32_t a1,
                                         uint32_t a2, uint32_t a3,
                                         uint32_t b0, uint32_t b1) {
    asm volatile("mma.sync.aligned.m16n8k16.row.col.f32.bf16.bf16.f32 "
                 "{%0,%1,%2,%3}, {%4,%5,%6,%7}, {%8,%9}, {%0,%1,%2,%3};"
                 : "+f"(c[0]), "+f"(c[1]), "+f"(c[2]), "+f"(c[3])
                 : "r"(a0), "r"(a1), "r"(a2), "r"(a3), "r"(b0), "r"(b1));
}
__device__ __forceinline__ uint32_t pk(int2 m) {
    return (uint32_t)(m.x + (m.y << 16)) * 0x3F80u;
}

// ---------------- prep v4: tables in smem, 1 thread = 1 user ----------------
__global__ void __launch_bounds__(256) prep_kernel(
        const unsigned int* __restrict__ us,
        const float* __restrict__ e0, const float* __restrict__ e1,
        const float* __restrict__ e2, const float* __restrict__ e3,
        const float* __restrict__ e4, const float* __restrict__ e5) {
    __shared__ float sTab[TFLOATS];
    __shared__ int s_is64;
    const int tid = threadIdx.x;

    if (tid == 0) {
        unsigned probe = 0;
#pragma unroll
        for (int w = 1; w < 32; w += 2) probe |= us[w];
        s_is64 = (probe == 0u);   // int64 serialization -> zero high words
    }
    // stage all 6 tables into smem (row starts: 0,222,249,622,905,931)
    const float* srcs[6] = {e0, e1, e2, e3, e4, e5};
    const int cnts[6] = {222 * 6, 27 * 6, 373 * 6, 283 * 6, 26 * 6, 7 * 6};
    const int offs[6] = {0, 222 * 6, 249 * 6, 622 * 6, 905 * 6, 931 * 6};
#pragma unroll
    for (int i = 0; i < 6; i++)
        for (int j = tid; j < cnts[i]; j += 256) sTab[offs[i] + j] = srcs[i][j];
    __syncthreads();

    const int u = blockIdx.x * 256 + tid;
    if (u >= UN) return;

    // load this user's 6 indices (coalesced)
    unsigned idx[6];
    if (s_is64) {
        const uint4* p = (const uint4*)us + (size_t)u * 3;    // 48B/user
        uint4 a = p[0], b = p[1], c = p[2];
        idx[0] = a.x; idx[1] = a.z; idx[2] = b.x; idx[3] = b.z; idx[4] = c.x; idx[5] = c.z;
    } else {
        const uint2* p = (const uint2*)(us + (size_t)u * 6);  // 24B/user, 8B-aligned
        uint2 a = p[0], b = p[1], c = p[2];
        idx[0] = a.x; idx[1] = a.y; idx[2] = b.x; idx[3] = b.y; idx[4] = c.x; idx[5] = c.y;
    }

    // output column: paired-word permutation within each 64-element k-block
    const int blk = u >> 6, pr = (u >> 1) & 31, d = u & 1;
    const int wp = ((pr >> 3) << 3) + ((pr & 3) << 1) + ((pr >> 2) & 1);
    __nv_bfloat16* base = g_UT + (size_t)blk * 64 + wp * 2 + d;

#pragma unroll
    for (int i = 0; i < 6; i++) {
        const float* row = sTab + offs[i] + (size_t)idx[i] * 6;
        float2 r0 = *(const float2*)row;
        float2 r1 = *(const float2*)(row + 2);
        float2 r2 = *(const float2*)(row + 4);
        base[(size_t)(6 * i + 0) * KPAD] = __float2bfloat16(r0.x);
        base[(size_t)(6 * i + 1) * KPAD] = __float2bfloat16(r0.y);
        base[(size_t)(6 * i + 2) * KPAD] = __float2bfloat16(r1.x);
        base[(size_t)(6 * i + 3) * KPAD] = __float2bfloat16(r1.y);
        base[(size_t)(6 * i + 4) * KPAD] = __float2bfloat16(r2.x);
        base[(size_t)(6 * i + 5) * KPAD] = __float2bfloat16(r2.y);
    }
    base[(size_t)36 * KPAD] = __float2bfloat16(1.0f);   // count row
}

// ---------------- accum: cp.async depth-2 HMMA GEMM, m32/warp ----------------
template <bool MG, bool KG>
__device__ __forceinline__ void issue_stage(uint32_t smb, int s, int k0,
                                            const int* __restrict__ tum,
                                            int t0, int tid) {
    uint32_t aB = smb + s * ASTAGE_B;
    uint32_t bB = smb + 2 * ASTAGE_B + s * BSTAGE_B;
#pragma unroll
    for (int i = 0; i < 16; i++) {
        int q = tid + i * NTHR;
        int r = q >> 4;
        int c = (q & 15) << 2;
        uint32_t dst = aB + (uint32_t)r * (ASTR * 4) + (uint32_t)(q & 15) * 16u;
        const int* src = tum + (size_t)(t0 + r) * UN + (k0 + c);
        if (MG || KG) {
            uint32_t sz = ((!MG || (t0 + r) < TN) && (!KG || (k0 + c) < UN)) ? 16u : 0u;
            asm volatile("cp.async.cg.shared.global [%0], [%1], 16, %2;"
                         :: "r"(dst), "l"(src), "r"(sz));
        } else {
            asm volatile("cp.async.cg.shared.global [%0], [%1], 16, 16;"
                         :: "r"(dst), "l"(src));
        }
    }
#pragma unroll
    for (int i = 0; i < 3; i++) {
        int q = tid + i * NTHR;
        if (q < NF * 8) {
            int r = q >> 3;
            uint32_t dst = bB + (uint32_t)r * (BSTR * 4) + (uint32_t)(q & 7) * 16u;
            const __nv_bfloat16* src = g_UT + (size_t)r * KPAD + k0 + (q & 7) * 8;
            asm volatile("cp.async.cg.shared.global [%0], [%1], 16, 16;"
                         :: "r"(dst), "l"(src));
        }
    }
}

__device__ __forceinline__ void issue_dispatch(uint32_t smb, int s, int k0,
                                               const int* __restrict__ tum,
                                               int t0, int tid, bool mg) {
    const bool kg = (k0 + KT2 > UN);
    if (mg) {
        if (kg) issue_stage<true, true>(smb, s, k0, tum, t0, tid);
        else    issue_stage<true, false>(smb, s, k0, tum, t0, tid);
    } else {
        if (kg) issue_stage<false, true>(smb, s, k0, tum, t0, tid);
        else    issue_stage<false, false>(smb, s, k0, tum, t0, tid);
    }
}

__device__ __forceinline__ void compute_stage(const char* sm, int s, float acc[2][5][4],
                                              int w, int g, int cc) {
    const int* aP = (const int*)(sm + s * ASTAGE_B);
    const uint32_t* bP = (const uint32_t*)(sm + 2 * ASTAGE_B + s * BSTAGE_B);
    const int rowA = (32 * w + g) * ASTR + 2 * cc;
#pragma unroll
    for (int ks = 0; ks < 4; ks++) {
        uint32_t bf[10];
        const uint32_t* bb = bP + g * BSTR + ks * 8 + cc * 2;
#pragma unroll
        for (int nb = 0; nb < 5; nb++) {
            uint2 v = *(const uint2*)(bb + nb * 8 * BSTR);
            bf[2 * nb] = v.x;
            bf[2 * nb + 1] = v.y;
        }
#pragma unroll
        for (int mh = 0; mh < 2; mh++) {
            const int* p0 = aP + rowA + mh * 16 * ASTR + 16 * ks;
            int2 x0 = *(const int2*)(p0);
            int2 x2 = *(const int2*)(p0 + 8);
            int2 x1 = *(const int2*)(p0 + 8 * ASTR);
            int2 x3 = *(const int2*)(p0 + 8 * ASTR + 8);
            uint32_t a0 = pk(x0), a1 = pk(x1), a2 = pk(x2), a3 = pk(x3);
#pragma unroll
            for (int nb = 0; nb < 5; nb++)
                mma16816(acc[mh][nb], a0, a1, a2, a3, bf[2 * nb], bf[2 * nb + 1]);
        }
    }
}

__global__ void __launch_bounds__(NTHR, 2) accum_kernel(const int* __restrict__ tum) {
    extern __shared__ char sm[];
    const int tid = threadIdx.x;
    const int w = tid >> 5, lane = tid & 31;
    const int g = lane >> 2, cc = lane & 3;
    const int mb = blockIdx.x & (NMB - 1);
    const int sp = blockIdx.x >> 4;
    const int t0 = mb * MB;
    const uint32_t smb = smem_u32(sm);
    const bool mg = (t0 + MB > TN);

    const int J = (NST_TOT - sp + NSPLIT - 1) / NSPLIT;

    float acc[2][5][4];
#pragma unroll
    for (int mh = 0; mh < 2; mh++)
#pragma unroll
        for (int nb = 0; nb < 5; nb++)
#pragma unroll
            for (int q = 0; q < 4; q++) acc[mh][nb][q] = 0.0f;

    issue_dispatch(smb, 0, sp * KT2, tum, t0, tid, mg);
    asm volatile("cp.async.commit_group;");

    for (int j = 0; j < J; j++) {
        __syncthreads();   // buffer (j+1)&1 free: compute(j-1) done by all warps
        if (j + 1 < J) {
            issue_dispatch(smb, (j + 1) & 1, (sp + (j + 1) * NSPLIT) * KT2, tum, t0, tid, mg);
            asm volatile("cp.async.commit_group;");
            asm volatile("cp.async.wait_group 1;");   // in-order: group j retired
        } else {
            asm volatile("cp.async.wait_group 0;");
        }
        __syncthreads();
        compute_stage(sm, j & 1, acc, w, g, cc);
    }

    float* part = g_part + (size_t)sp * TPAD * NF;
#pragma unroll
    for (int mh = 0; mh < 2; mh++) {
        int tA = t0 + 32 * w + 16 * mh + g;
#pragma unroll
        for (int nb = 0; nb < 5; nb++) {
            int col = nb * 8 + 2 * cc;
            if (tA < TN)
                *(float2*)(&part[(size_t)tA * NF + col]) =
                    make_float2(acc[mh][nb][0], acc[mh][nb][1]);
            if (tA + 8 < TN)
                *(float2*)(&part[(size_t)(tA + 8) * NF + col]) =
                    make_float2(acc[mh][nb][2], acc[mh][nb][3]);
        }
    }
}

// ---------------- finalize ----------------
__global__ void finalize_kernel(const float* __restrict__ T_static,
                                float* __restrict__ out) {
    int i = blockIdx.x * blockDim.x + threadIdx.x;
    if (i >= TN * OUTC) return;
    int t = i / OUTC;
    int c = i - t * OUTC;
    if (c < TF) {
        out[i] = T_static[t * TF + c];
    } else {
        int f = c - TF;
        float s = 0.0f, cnt = 0.0f;
        const float* base = g_part + (size_t)t * NF;
#pragma unroll
        for (int k = 0; k < NSPLIT; k++) {
            const float* q = base + (size_t)k * (TPAD * NF);
            s += q[f];
            cnt += q[36];
        }
        out[i] = s / cnt;
    }
}

extern "C" void kernel_launch(void* const* d_in, const int* in_sizes, int n_in,
                              void* d_out, int out_size) {
    const float* T_static = (const float*)d_in[0];
    const unsigned int* us = (const unsigned int*)d_in[1];
    const int* tum = (const int*)d_in[2];
    const float* e0 = (const float*)d_in[3];
    const float* e1 = (const float*)d_in[4];
    const float* e2 = (const float*)d_in[5];
    const float* e3 = (const float*)d_in[6];
    const float* e4 = (const float*)d_in[7];
    const float* e5 = (const float*)d_in[8];
    float* out = (float*)d_out;

    cudaFuncSetAttribute(accum_kernel, cudaFuncAttributeMaxDynamicSharedMemorySize,
                         SMEM_TOTAL);
    prep_kernel<<<(UN + 255) / 256, 256>>>(us, e0, e1, e2, e3, e4, e5);
    accum_kernel<<<NMB * NSPLIT, NTHR, SMEM_TOTAL>>>(tum);
    finalize_kernel<<<(TN * OUTC + 255) / 256, 256>>>(T_static, out);
}